// round 13
// baseline (speedup 1.0000x reference)
#include <cuda_runtime.h>
#include <cuda_fp16.h>
#include <math.h>
#include <float.h>
#include <stdint.h>

#define N_ROWS   8192
#define C_DIM    256
#define K_CODES  16384
#define OUT_EMB  2097152
#define GRID_P   148
#define N_TILES  4096    // n-major: T = n*64 + m
#define M_MARGIN 0.25f

// ---------------- scratch (static, no allocations) ----------------
__device__ __align__(16) __half g_zh[N_ROWS * C_DIM];
__device__ __align__(16) __half g_eh[K_CODES * C_DIM];
__device__ __align__(16) float g_enorm[K_CODES];
__device__ unsigned long long g_pb[64 * N_ROWS];   // per (nCol,row) best key
__device__ unsigned long long g_ps[64 * N_ROWS];   // per (nCol,row) 2nd key
__device__ unsigned long long g_fix[N_ROWS];
__device__ int    g_idx[N_ROWS];
__device__ unsigned char g_flagged[N_ROWS];
__device__ int    g_list[N_ROWS];
__device__ int    g_nflag;
__device__ int    g_hist[K_CODES];
__device__ double g_accum;

// ---------------- PTX helpers (compute_100-legal) ----------------
__device__ __forceinline__ uint32_t smem_u32(const void* p) {
    uint32_t a;
    asm("{ .reg .u64 t; cvta.to.shared.u64 t, %1; cvt.u32.u64 %0, t; }"
        : "=r"(a) : "l"(p));
    return a;
}
__device__ __forceinline__ void cp_async16(uint32_t saddr, const void* gaddr) {
    asm volatile("cp.async.cg.shared.global [%0], [%1], 16;\n"
                 :: "r"(saddr), "l"(gaddr));
}
__device__ __forceinline__ void cp_commit() {
    asm volatile("cp.async.commit_group;\n");
}
template <int N>
__device__ __forceinline__ void cp_wait() {
    asm volatile("cp.async.wait_group %0;\n" :: "n"(N));
}
__device__ __forceinline__ void ldsm4(uint32_t* r, uint32_t addr) {
    asm volatile("ldmatrix.sync.aligned.m8n8.x4.shared.b16 {%0,%1,%2,%3}, [%4];"
                 : "=r"(r[0]), "=r"(r[1]), "=r"(r[2]), "=r"(r[3]) : "r"(addr));
}
__device__ __forceinline__ void mma_f16(float* d, const uint32_t* a,
                                        uint32_t b0, uint32_t b1) {
    asm("mma.sync.aligned.m16n8k16.row.col.f32.f16.f16.f32 "
        "{%0,%1,%2,%3}, {%4,%5,%6,%7}, {%8,%9}, {%0,%1,%2,%3};"
        : "+f"(d[0]), "+f"(d[1]), "+f"(d[2]), "+f"(d[3])
        : "r"(a[0]), "r"(a[1]), "r"(a[2]), "r"(a[3]), "r"(b0), "r"(b1));
}
__device__ __forceinline__ uint32_t fkey(float v) {
    uint32_t u = __float_as_uint(v);
    return (u & 0x80000000u) ? ~u : (u | 0x80000000u);
}
__device__ __forceinline__ float unfkey(uint32_t f) {
    return __uint_as_float((f & 0x80000000u) ? (f ^ 0x80000000u) : ~f);
}

// ------- z [B,C,T,H,W] -> zh fp16 [N, C]; also does global init -------
__global__ void split_z(const float* __restrict__ z) {
    __shared__ float s[32][33];
    // fused init (graph order guarantees these are consumed post-gemm)
    int flat = (blockIdx.x * 8 + blockIdx.y) * 256 +
               threadIdx.y * 32 + threadIdx.x;
    if (flat < K_CODES) g_hist[flat] = 0;
    if (flat < N_ROWS) {
        g_fix[flat] = 0xFFFFFFFFFFFFFFFFull;
        g_flagged[flat] = 0;
    }
    if (flat == 0) { g_accum = 0.0; g_nflag = 0; }

    int n0 = blockIdx.x * 32, c0 = blockIdx.y * 32;
    int tx = threadIdx.x, ty = threadIdx.y;
#pragma unroll
    for (int k = 0; k < 4; k++) {
        int yy = ty + k * 8;
        int c = c0 + yy;
        int n = n0 + tx;
        int b = n >> 11, thw = n & 2047;
        s[yy][tx] = z[((b * C_DIM + c) << 11) + thw];
    }
    __syncthreads();
#pragma unroll
    for (int k = 0; k < 4; k++) {
        int yy = ty + k * 8;
        g_zh[(n0 + yy) * C_DIM + c0 + tx] = __float2half_rn(s[tx][yy]);
    }
}

// ---------------- emb -> eh fp16 + ||e||^2 --------------------------
__global__ void split_e(const float* __restrict__ emb) {
    int w = (blockIdx.x * blockDim.x + threadIdx.x) >> 5;
    int lane = threadIdx.x & 31;
    if (w >= K_CODES) return;
    const float4* e4 = (const float4*)(emb + (size_t)w * C_DIM);
    __half2* h2 = (__half2*)(g_eh + (size_t)w * C_DIM);
    float s = 0.f;
#pragma unroll
    for (int q = 0; q < 2; q++) {
        float4 v = e4[q * 32 + lane];
        s += v.x * v.x + v.y * v.y + v.z * v.z + v.w * v.w;
        h2[(q * 32 + lane) * 2 + 0] =
            __halves2half2(__float2half_rn(v.x), __float2half_rn(v.y));
        h2[(q * 32 + lane) * 2 + 1] =
            __halves2half2(__float2half_rn(v.z), __float2half_rn(v.w));
    }
#pragma unroll
    for (int o = 16; o > 0; o >>= 1) s += __shfl_down_sync(0xffffffffu, s, o);
    if (lane == 0) g_enorm[w] = s;
}

// ---------------- persistent 1-term FP16 GEMM + top-2 argmin --------
// 148 persistent CTAs; contiguous n-major tile runs so consecutive tiles
// share the B (codes) tile -> B reloaded only at n-column boundaries.
// Tile 128(M) x 256(N); 8 warps 2x4, warp 64x64; 2 k-chunks of 128.
#define STAGE_BYTES 98304
#define CTRL_OFF    196608
#define SMEM_TOTAL  204800

__global__ void __launch_bounds__(256, 1)
vq_gemm() {
    extern __shared__ __align__(1024) char smem[];
    const uint32_t sb = smem_u32(smem);
    const int tid = threadIdx.x;
    const int wid = tid >> 5, l = tid & 31;
    const int warpM = wid >> 2, warpN = wid & 3;

    unsigned long long* sv1 = (unsigned long long*)(smem + CTRL_OFF);
    unsigned long long* sv2 = (unsigned long long*)(smem + CTRL_OFF + 4096);

    uint32_t aoff[4], boff[4];
    int a7[4], b7[4];
#pragma unroll
    for (int mt = 0; mt < 4; mt++) {
        int row = warpM * 64 + mt * 16 + ((l >> 3) & 1) * 8 + (l & 7);
        aoff[mt] = (uint32_t)(row * 256);
        a7[mt] = row & 7;
    }
#pragma unroll
    for (int ntp = 0; ntp < 4; ntp++) {
        int row = warpN * 64 + ntp * 16 + ((l >> 3) & 1) * 8 + (l & 7);
        boff[ntp] = (uint32_t)(row * 256);
        b7[ntp] = row & 7;
    }
    const int segbit = l >> 4;

    const int bid = blockIdx.x;
    const int tS = (bid * N_TILES) / GRID_P;
    const int tE = ((bid + 1) * N_TILES) / GRID_P;
    const int P = (tE - tS) * 2;

    // position p -> tile T = tS + (p>>1); T = n*64 + m (n-major)
    auto load_pos = [&](int p) {
        const int j = p >> 1;
        const int T = tS + j;
        const int m0 = (T & 63) << 7;
        const int k0 = (p & 1) << 7;
        const uint32_t base = sb + (p & 1) * STAGE_BYTES;
#pragma unroll
        for (int q = 0; q < 8; q++) {       // A: 128 rows x 256 B
            int idx = q * 256 + tid;
            int row = idx >> 4, seg = idx & 15;
            uint32_t so = (uint32_t)(row * 256 + ((seg ^ (row & 7)) << 4));
            size_t go = (size_t)(m0 + row) * C_DIM + k0 + seg * 8;
            cp_async16(base + so, g_zh + go);
        }
        if (j == 0 || (T & 63) == 0) {      // B only at n-column start
            const int n0 = (T >> 6) << 8;
#pragma unroll
            for (int q = 0; q < 16; q++) {  // B: 256 rows x 256 B
                int idx = q * 256 + tid;
                int row = idx >> 4, seg = idx & 15;
                uint32_t so = (uint32_t)(row * 256 + ((seg ^ (row & 7)) << 4));
                size_t go = (size_t)(n0 + row) * C_DIM + k0 + seg * 8;
                cp_async16(base + 32768 + so, g_eh + go);
            }
        }
        cp_commit();
    };

    float acc[4][8][4];
#pragma unroll
    for (int mt = 0; mt < 4; mt++)
#pragma unroll
        for (int nt = 0; nt < 8; nt++)
#pragma unroll
            for (int r = 0; r < 4; r++) acc[mt][nt][r] = 0.f;

    if (P > 0) load_pos(0);
    if (P > 1) load_pos(1);

    for (int p = 0; p < P; p++) {
        if (p + 1 < P) cp_wait<1>(); else cp_wait<0>();
        __syncthreads();
        const uint32_t base = sb + (p & 1) * STAGE_BYTES;

#pragma unroll
        for (int ks = 0; ks < 8; ks++) {
            const int seg = 2 * ks + segbit;
            uint32_t Ah[4][4];
#pragma unroll
            for (int mt = 0; mt < 4; mt++)
                ldsm4(Ah[mt], base + aoff[mt] + (uint32_t)((seg ^ a7[mt]) << 4));
#pragma unroll
            for (int ntp = 0; ntp < 4; ntp++) {
                uint32_t Bh[4];
                ldsm4(Bh, base + 32768 + boff[ntp] +
                           (uint32_t)((seg ^ b7[ntp]) << 4));
#pragma unroll
                for (int sub = 0; sub < 2; sub++)
#pragma unroll
                    for (int mt = 0; mt < 4; mt++)
                        mma_f16(acc[mt][ntp * 2 + sub], Ah[mt],
                                Bh[sub], Bh[sub + 2]);
            }
        }
        __syncthreads();
        if (p + 2 < P) load_pos(p + 2);

        if ((p & 1) == 1) {
            // ---- tile epilogue: per-row top-2, float-guarded ----
            const int T = tS + (p >> 1);
            const int m0 = (T & 63) << 7;
            const int n0 = (T >> 6) << 8;
            const int nCol = T >> 6;
#pragma unroll
            for (int s = 0; s < 8; s++) {
                const int mt = s >> 1, half = s & 1;
                const int rloc = warpM * 64 + mt * 16 + half * 8 + (l >> 2);
                unsigned long long k1 = 0xFFFFFFFFFFFFFFFFull;
                unsigned long long k2 = 0xFFFFFFFFFFFFFFFFull;
                float v2f = INFINITY;
#pragma unroll
                for (int nt = 0; nt < 8; nt++)
#pragma unroll
                    for (int j = 0; j < 2; j++) {
                        int cl = warpN * 64 + (nt >> 1) * 16 + (nt & 1) * 8 +
                                 2 * (l & 3) + j;
                        float d = __ldg(&g_enorm[n0 + cl]) -
                                  2.0f * acc[mt][nt][half * 2 + j];
                        acc[mt][nt][half * 2 + j] = 0.f;
                        if (d <= v2f) {      // rare slow path
                            unsigned long long key =
                                ((unsigned long long)fkey(d) << 32) |
                                (unsigned)(n0 + cl);
                            if (key < k1) { k2 = k1; k1 = key; }
                            else if (key < k2) { k2 = key; }
                            uint32_t hi = (uint32_t)(k2 >> 32);
                            v2f = (hi == 0xFFFFFFFFu) ? INFINITY : unfkey(hi);
                        }
                    }
#pragma unroll
                for (int off = 1; off <= 2; off <<= 1) {
                    unsigned long long o1 =
                        __shfl_xor_sync(0xffffffffu, k1, off);
                    unsigned long long o2 =
                        __shfl_xor_sync(0xffffffffu, k2, off);
                    unsigned long long hi = (k1 > o1) ? k1 : o1;
                    k1 = (k1 < o1) ? k1 : o1;
                    unsigned long long lo2 = (k2 < o2) ? k2 : o2;
                    k2 = (hi < lo2) ? hi : lo2;
                }
                if ((l & 3) == 0) {
                    sv1[warpN * 128 + rloc] = k1;
                    sv2[warpN * 128 + rloc] = k2;
                }
            }
            __syncthreads();
            if (tid < 128) {
                unsigned long long K1 = sv1[tid];
                unsigned long long K2 = sv2[tid];
#pragma unroll
                for (int w = 1; w < 4; w++) {
                    unsigned long long b1 = sv1[w * 128 + tid];
                    unsigned long long b2 = sv2[w * 128 + tid];
                    unsigned long long hi = (K1 > b1) ? K1 : b1;
                    K1 = (K1 < b1) ? K1 : b1;
                    unsigned long long lo2 = (K2 < b2) ? K2 : b2;
                    K2 = (hi < lo2) ? hi : lo2;
                }
                g_pb[nCol * N_ROWS + m0 + tid] = K1;
                g_ps[nCol * N_ROWS + m0 + tid] = K2;
            }
        }
    }
}

// ---------------- merge: global top-2 per row, flag close rows ------
__global__ void merge_kernel() {
    int n = blockIdx.x * blockDim.x + threadIdx.x;
    if (n >= N_ROWS) return;
    unsigned long long k1 = 0xFFFFFFFFFFFFFFFFull;
    unsigned long long k2 = 0xFFFFFFFFFFFFFFFFull;
    int cstar = 0;
    for (int c = 0; c < 64; c++) {
        unsigned long long kb = g_pb[c * N_ROWS + n];
        if (kb < k1) { k2 = k1; k1 = kb; cstar = c; }
        else if (kb < k2) { k2 = kb; }
    }
    unsigned long long ks2 = g_ps[cstar * N_ROWS + n];
    if (ks2 < k2) k2 = ks2;
    g_idx[n] = (int)(k1 & 0xFFFFFFFFull);
    float v1 = unfkey((uint32_t)(k1 >> 32));
    float v2 = unfkey((uint32_t)(k2 >> 32));
    if (v2 - v1 < M_MARGIN) {
        g_flagged[n] = 1;
        int pos = atomicAdd(&g_nflag, 1);
        if (pos < N_ROWS) g_list[pos] = n;
    }
}

// ------- exact fp32 rescue over the 128 stored candidates/row -------
__global__ void fixup_kernel(const float* __restrict__ z,
                             const float* __restrict__ emb) {
    __shared__ __align__(16) float zbuf[8][256];
    int nf = g_nflag;
    if (nf > N_ROWS) nf = N_ROWS;
    const int wid = threadIdx.x >> 5, lane = threadIdx.x & 31;
    const int gw = blockIdx.x * 8 + wid;

    for (int i = gw; i < nf; i += 64 * 8) {
        int n = g_list[i];
        int b = n >> 11, thw = n & 2047;
#pragma unroll
        for (int j = 0; j < 8; j++) {
            int c = j * 32 + lane;
            zbuf[wid][c] = z[((b * C_DIM + c) << 11) + thw];
        }
        __syncwarp();
        unsigned long long bestk = 0xFFFFFFFFFFFFFFFFull;
#pragma unroll
        for (int j = 0; j < 4; j++) {
            int slot = j * 32 + lane;   // 0..127 candidates
            unsigned long long key = (slot < 64)
                ? g_pb[slot * N_ROWS + n]
                : g_ps[(slot - 64) * N_ROWS + n];
            int c = (int)(key & 0xFFFFFFFFull);
            const float4* e4 = (const float4*)(emb + (size_t)c * C_DIM);
            float dot = 0.f;
#pragma unroll 8
            for (int d4 = 0; d4 < 64; d4++) {
                float4 e = e4[d4];
                float4 zv = ((const float4*)zbuf[wid])[d4];
                dot = fmaf(zv.x, e.x, dot);
                dot = fmaf(zv.y, e.y, dot);
                dot = fmaf(zv.z, e.z, dot);
                dot = fmaf(zv.w, e.w, dot);
            }
            float dist = __ldg(&g_enorm[c]) - 2.0f * dot;
            unsigned long long k2 =
                ((unsigned long long)fkey(dist) << 32) | (unsigned)c;
            if (k2 < bestk) bestk = k2;
        }
#pragma unroll
        for (int off = 16; off > 0; off >>= 1) {
            unsigned long long o = __shfl_xor_sync(0xffffffffu, bestk, off);
            if (o < bestk) bestk = o;
        }
        if (lane == 0) atomicMin(&g_fix[n], bestk);
        __syncwarp();
    }
}

// ------- gather + channels-first output + loss + histogram ---------
__global__ void out_kernel(const float* __restrict__ z,
                           const float* __restrict__ emb,
                           float* __restrict__ out) {
    int i = blockIdx.x * blockDim.x + threadIdx.x;
    int b = i >> 19;
    int rem = i & 524287;
    int c = rem >> 11;
    int thw = rem & 2047;
    int n = (b << 11) | thw;
    int idx = g_idx[n];
    if (g_flagged[n]) idx = (int)(g_fix[n] & 0xFFFFFFFFull);
    float e = emb[(size_t)idx * C_DIM + c];
    out[i] = e;
    if (c == 0) {
        out[OUT_EMB + n] = (float)idx;
        atomicAdd(&g_hist[idx], 1);
    }
    float d = z[i] - e;
    float ss = d * d;
#pragma unroll
    for (int o = 16; o > 0; o >>= 1) ss += __shfl_down_sync(0xffffffffu, ss, o);
    __shared__ float ws[8];
    int lane = threadIdx.x & 31, warp = threadIdx.x >> 5;
    if (lane == 0) ws[warp] = ss;
    __syncthreads();
    if (threadIdx.x < 8) {
        float v = ws[threadIdx.x];
#pragma unroll
        for (int o = 4; o > 0; o >>= 1) v += __shfl_down_sync(0xffu, v, o);
        if (threadIdx.x == 0) atomicAdd(&g_accum, (double)v);
    }
}

// ---------------- perplexity + loss finalize ----------------
__global__ void final_kernel(float* __restrict__ out) {
    __shared__ float ws[8];
    int tid = threadIdx.x;
    float s = 0.f;
    for (int k = tid; k < K_CODES; k += 256) {
        float p = (float)g_hist[k] * (1.0f / N_ROWS);
        s += p * logf(p + 1e-10f);
    }
#pragma unroll
    for (int o = 16; o > 0; o >>= 1) s += __shfl_down_sync(0xffffffffu, s, o);
    int lane = tid & 31, warp = tid >> 5;
    if (lane == 0) ws[warp] = s;
    __syncthreads();
    if (tid < 8) {
        float v = ws[tid];
#pragma unroll
        for (int o = 4; o > 0; o >>= 1) v += __shfl_down_sync(0xffu, v, o);
        if (tid == 0) {
            out[OUT_EMB + N_ROWS]     = 0.25f * (float)(g_accum * (1.0 / 2097152.0));
            out[OUT_EMB + N_ROWS + 1] = expf(-v);
        }
    }
}

// ---------------- launch ----------------
extern "C" void kernel_launch(void* const* d_in, const int* in_sizes, int n_in,
                              void* d_out, int out_size) {
    const float* z = (const float*)d_in[0];
    const float* emb = (const float*)d_in[1];
    if (in_sizes[0] == K_CODES * C_DIM && in_sizes[1] == N_ROWS * C_DIM) {
        z = (const float*)d_in[1];
        emb = (const float*)d_in[0];
    }
    float* out = (float*)d_out;

    cudaFuncSetAttribute(vq_gemm, cudaFuncAttributeMaxDynamicSharedMemorySize,
                         SMEM_TOTAL);

    split_z<<<dim3(256, 8), dim3(32, 8)>>>(z);
    split_e<<<2048, 256>>>(emb);
    vq_gemm<<<GRID_P, 256, SMEM_TOTAL>>>();
    merge_kernel<<<32, 256>>>();
    fixup_kernel<<<64, 256>>>(z, emb);
    out_kernel<<<8192, 256>>>(z, emb, out);
    final_kernel<<<1, 256>>>(out);
}

// round 14
// speedup vs baseline: 1.3353x; 1.3353x over previous
#include <cuda_runtime.h>
#include <cuda_fp16.h>
#include <math.h>
#include <float.h>
#include <stdint.h>

#define N_ROWS   8192
#define C_DIM    256
#define K_CODES  16384
#define OUT_EMB  2097152
#define GRID_P   148
#define N_TILES  4096    // 64 m-tiles x 64 n-tiles
#define M_MARGIN 0.25f

// ---------------- scratch (static, no allocations) ----------------
__device__ __align__(16) __half g_zh[N_ROWS * C_DIM];
__device__ __align__(16) __half g_eh[K_CODES * C_DIM];
__device__ __align__(16) float g_enorm[K_CODES];
__device__ unsigned long long g_pb[64 * N_ROWS];   // per (nCTA,row) best key
__device__ unsigned long long g_ps[64 * N_ROWS];   // per (nCTA,row) 2nd key
__device__ unsigned long long g_fix[N_ROWS];
__device__ int    g_idx[N_ROWS];
__device__ unsigned char g_flagged[N_ROWS];
__device__ int    g_list[N_ROWS];
__device__ int    g_nflag;
__device__ int    g_hist[K_CODES];
__device__ double g_accum;

// ---------------- PTX helpers (compute_100-legal) ----------------
__device__ __forceinline__ uint32_t smem_u32(const void* p) {
    uint32_t a;
    asm("{ .reg .u64 t; cvta.to.shared.u64 t, %1; cvt.u32.u64 %0, t; }"
        : "=r"(a) : "l"(p));
    return a;
}
__device__ __forceinline__ void cp_async16(uint32_t saddr, const void* gaddr) {
    asm volatile("cp.async.cg.shared.global [%0], [%1], 16;\n"
                 :: "r"(saddr), "l"(gaddr));
}
__device__ __forceinline__ void cp_commit() {
    asm volatile("cp.async.commit_group;\n");
}
template <int N>
__device__ __forceinline__ void cp_wait() {
    asm volatile("cp.async.wait_group %0;\n" :: "n"(N));
}
__device__ __forceinline__ void ldsm4(uint32_t* r, uint32_t addr) {
    asm volatile("ldmatrix.sync.aligned.m8n8.x4.shared.b16 {%0,%1,%2,%3}, [%4];"
                 : "=r"(r[0]), "=r"(r[1]), "=r"(r[2]), "=r"(r[3]) : "r"(addr));
}
__device__ __forceinline__ void mma_f16(float* d, const uint32_t* a,
                                        uint32_t b0, uint32_t b1) {
    asm("mma.sync.aligned.m16n8k16.row.col.f32.f16.f16.f32 "
        "{%0,%1,%2,%3}, {%4,%5,%6,%7}, {%8,%9}, {%0,%1,%2,%3};"
        : "+f"(d[0]), "+f"(d[1]), "+f"(d[2]), "+f"(d[3])
        : "r"(a[0]), "r"(a[1]), "r"(a[2]), "r"(a[3]), "r"(b0), "r"(b1));
}
__device__ __forceinline__ uint32_t fkey(float v) {
    uint32_t u = __float_as_uint(v);
    return (u & 0x80000000u) ? ~u : (u | 0x80000000u);
}
__device__ __forceinline__ float unfkey(uint32_t f) {
    return __uint_as_float((f & 0x80000000u) ? (f ^ 0x80000000u) : ~f);
}

// ------- z [B,C,T,H,W] -> zh fp16 [N, C]; also does global init -------
__global__ void split_z(const float* __restrict__ z) {
    __shared__ float s[32][33];
    int flat = (blockIdx.x * 8 + blockIdx.y) * 256 +
               threadIdx.y * 32 + threadIdx.x;
    if (flat < K_CODES) g_hist[flat] = 0;
    if (flat < N_ROWS) {
        g_fix[flat] = 0xFFFFFFFFFFFFFFFFull;
        g_flagged[flat] = 0;
    }
    if (flat == 0) { g_accum = 0.0; g_nflag = 0; }

    int n0 = blockIdx.x * 32, c0 = blockIdx.y * 32;
    int tx = threadIdx.x, ty = threadIdx.y;
#pragma unroll
    for (int k = 0; k < 4; k++) {
        int yy = ty + k * 8;
        int c = c0 + yy;
        int n = n0 + tx;
        int b = n >> 11, thw = n & 2047;
        s[yy][tx] = z[((b * C_DIM + c) << 11) + thw];
    }
    __syncthreads();
#pragma unroll
    for (int k = 0; k < 4; k++) {
        int yy = ty + k * 8;
        g_zh[(n0 + yy) * C_DIM + c0 + tx] = __float2half_rn(s[tx][yy]);
    }
}

// ---------------- emb -> eh fp16 + ||e||^2 --------------------------
__global__ void split_e(const float* __restrict__ emb) {
    int w = (blockIdx.x * blockDim.x + threadIdx.x) >> 5;
    int lane = threadIdx.x & 31;
    if (w >= K_CODES) return;
    const float4* e4 = (const float4*)(emb + (size_t)w * C_DIM);
    __half2* h2 = (__half2*)(g_eh + (size_t)w * C_DIM);
    float s = 0.f;
#pragma unroll
    for (int q = 0; q < 2; q++) {
        float4 v = e4[q * 32 + lane];
        s += v.x * v.x + v.y * v.y + v.z * v.z + v.w * v.w;
        h2[(q * 32 + lane) * 2 + 0] =
            __halves2half2(__float2half_rn(v.x), __float2half_rn(v.y));
        h2[(q * 32 + lane) * 2 + 1] =
            __halves2half2(__float2half_rn(v.z), __float2half_rn(v.w));
    }
#pragma unroll
    for (int o = 16; o > 0; o >>= 1) s += __shfl_down_sync(0xffffffffu, s, o);
    if (lane == 0) g_enorm[w] = s;
}

// ---------------- persistent 1-term FP16 GEMM + top-2 argmin --------
// 148 persistent CTAs; tile 128(M) x 256(N); 8 warps 2(M) x 4(N), 64x64.
// Tile = 2 k-chunks of 128; cp.async double-buffer pipelined across tiles.
// (R11-proven structure: A and B both loaded every position.)
#define STAGE_BYTES 98304
#define CTRL_OFF    196608
#define SMEM_TOTAL  204800

__global__ void __launch_bounds__(256, 1)
vq_gemm() {
    extern __shared__ __align__(1024) char smem[];
    const uint32_t sb = smem_u32(smem);
    const int tid = threadIdx.x;
    const int wid = tid >> 5, l = tid & 31;
    const int warpM = wid >> 2, warpN = wid & 3;

    unsigned long long* sv1 = (unsigned long long*)(smem + CTRL_OFF);
    unsigned long long* sv2 = (unsigned long long*)(smem + CTRL_OFF + 4096);

    uint32_t aoff[4], boff[4];
    int a7[4], b7[4];
#pragma unroll
    for (int mt = 0; mt < 4; mt++) {
        int row = warpM * 64 + mt * 16 + ((l >> 3) & 1) * 8 + (l & 7);
        aoff[mt] = (uint32_t)(row * 256);
        a7[mt] = row & 7;
    }
#pragma unroll
    for (int ntp = 0; ntp < 4; ntp++) {
        int row = warpN * 64 + ntp * 16 + ((l >> 3) & 1) * 8 + (l & 7);
        boff[ntp] = (uint32_t)(row * 256);
        b7[ntp] = row & 7;
    }
    const int segbit = l >> 4;

    const int bid = blockIdx.x;
    const int cnt = (N_TILES - bid + GRID_P - 1) / GRID_P;
    const int P = cnt * 2;

    auto load_pos = [&](int p) {
        const int t = bid + (p >> 1) * GRID_P;
        const int m0 = (t >> 6) << 7;
        const int n0 = (t & 63) << 8;
        const int k0 = (p & 1) * 128;
        const uint32_t base = sb + (p & 1) * STAGE_BYTES;
#pragma unroll
        for (int q = 0; q < 8; q++) {
            int idx = q * 256 + tid;
            int row = idx >> 4, seg = idx & 15;
            uint32_t so = (uint32_t)(row * 256 + ((seg ^ (row & 7)) << 4));
            size_t go = (size_t)(m0 + row) * C_DIM + k0 + seg * 8;
            cp_async16(base + so, g_zh + go);
        }
#pragma unroll
        for (int q = 0; q < 16; q++) {
            int idx = q * 256 + tid;
            int row = idx >> 4, seg = idx & 15;
            uint32_t so = (uint32_t)(row * 256 + ((seg ^ (row & 7)) << 4));
            size_t go = (size_t)(n0 + row) * C_DIM + k0 + seg * 8;
            cp_async16(base + 32768 + so, g_eh + go);
        }
        cp_commit();
    };

    float acc[4][8][4];
#pragma unroll
    for (int mt = 0; mt < 4; mt++)
#pragma unroll
        for (int nt = 0; nt < 8; nt++)
#pragma unroll
            for (int r = 0; r < 4; r++) acc[mt][nt][r] = 0.f;

    if (P > 0) load_pos(0);
    if (P > 1) load_pos(1);

    for (int p = 0; p < P; p++) {
        if (p + 1 < P) cp_wait<1>(); else cp_wait<0>();
        __syncthreads();
        const uint32_t base = sb + (p & 1) * STAGE_BYTES;

#pragma unroll
        for (int ks = 0; ks < 8; ks++) {
            const int seg = 2 * ks + segbit;
            uint32_t Ah[4][4];
#pragma unroll
            for (int mt = 0; mt < 4; mt++)
                ldsm4(Ah[mt], base + aoff[mt] + (uint32_t)((seg ^ a7[mt]) << 4));
#pragma unroll
            for (int ntp = 0; ntp < 4; ntp++) {
                uint32_t Bh[4];
                ldsm4(Bh, base + 32768 + boff[ntp] +
                           (uint32_t)((seg ^ b7[ntp]) << 4));
#pragma unroll
                for (int sub = 0; sub < 2; sub++)
#pragma unroll
                    for (int mt = 0; mt < 4; mt++)
                        mma_f16(acc[mt][ntp * 2 + sub], Ah[mt],
                                Bh[sub], Bh[sub + 2]);
            }
        }
        __syncthreads();
        if (p + 2 < P) load_pos(p + 2);

        if ((p & 1) == 1) {
            const int t = bid + (p >> 1) * GRID_P;
            const int m0 = (t >> 6) << 7;
            const int n0 = (t & 63) << 8;
            const int nIdx = t & 63;
#pragma unroll
            for (int s = 0; s < 8; s++) {
                const int mt = s >> 1, half = s & 1;
                const int rloc = warpM * 64 + mt * 16 + half * 8 + (l >> 2);
                unsigned long long k1 = 0xFFFFFFFFFFFFFFFFull;
                unsigned long long k2 = 0xFFFFFFFFFFFFFFFFull;
#pragma unroll
                for (int nt = 0; nt < 8; nt++)
#pragma unroll
                    for (int j = 0; j < 2; j++) {
                        int cl = warpN * 64 + (nt >> 1) * 16 + (nt & 1) * 8 +
                                 2 * (l & 3) + j;
                        float d = __ldg(&g_enorm[n0 + cl]) -
                                  2.0f * acc[mt][nt][half * 2 + j];
                        acc[mt][nt][half * 2 + j] = 0.f;
                        unsigned long long key =
                            ((unsigned long long)fkey(d) << 32) |
                            (unsigned)(n0 + cl);
                        if (key < k1) { k2 = k1; k1 = key; }
                        else if (key < k2) { k2 = key; }
                    }
#pragma unroll
                for (int off = 1; off <= 2; off <<= 1) {
                    unsigned long long o1 =
                        __shfl_xor_sync(0xffffffffu, k1, off);
                    unsigned long long o2 =
                        __shfl_xor_sync(0xffffffffu, k2, off);
                    unsigned long long hi = (k1 > o1) ? k1 : o1;
                    k1 = (k1 < o1) ? k1 : o1;
                    unsigned long long lo2 = (k2 < o2) ? k2 : o2;
                    k2 = (hi < lo2) ? hi : lo2;
                }
                if ((l & 3) == 0) {
                    sv1[warpN * 128 + rloc] = k1;
                    sv2[warpN * 128 + rloc] = k2;
                }
            }
            __syncthreads();
            if (tid < 128) {
                unsigned long long K1 = sv1[tid];
                unsigned long long K2 = sv2[tid];
#pragma unroll
                for (int w = 1; w < 4; w++) {
                    unsigned long long b1 = sv1[w * 128 + tid];
                    unsigned long long b2 = sv2[w * 128 + tid];
                    unsigned long long hi = (K1 > b1) ? K1 : b1;
                    K1 = (K1 < b1) ? K1 : b1;
                    unsigned long long lo2 = (K2 < b2) ? K2 : b2;
                    K2 = (hi < lo2) ? hi : lo2;
                }
                g_pb[nIdx * N_ROWS + m0 + tid] = K1;
                g_ps[nIdx * N_ROWS + m0 + tid] = K2;
            }
        }
    }
}

// ---------------- merge: global top-2 per row, flag close rows ------
__global__ void merge_kernel() {
    int n = blockIdx.x * blockDim.x + threadIdx.x;
    if (n >= N_ROWS) return;
    unsigned long long k1 = 0xFFFFFFFFFFFFFFFFull;
    unsigned long long k2 = 0xFFFFFFFFFFFFFFFFull;
    int cstar = 0;
    for (int c = 0; c < 64; c++) {
        unsigned long long kb = g_pb[c * N_ROWS + n];
        if (kb < k1) { k2 = k1; k1 = kb; cstar = c; }
        else if (kb < k2) { k2 = kb; }
    }
    unsigned long long ks2 = g_ps[cstar * N_ROWS + n];
    if (ks2 < k2) k2 = ks2;
    g_idx[n] = (int)(k1 & 0xFFFFFFFFull);
    float v1 = unfkey((uint32_t)(k1 >> 32));
    float v2 = unfkey((uint32_t)(k2 >> 32));
    if (v2 - v1 < M_MARGIN) {
        g_flagged[n] = 1;
        int pos = atomicAdd(&g_nflag, 1);
        if (pos < N_ROWS) g_list[pos] = n;
    }
}

// ------- exact fp32 rescue over the 128 stored candidates/row -------
__global__ void fixup_kernel(const float* __restrict__ z,
                             const float* __restrict__ emb) {
    __shared__ __align__(16) float zbuf[8][256];
    int nf = g_nflag;
    if (nf > N_ROWS) nf = N_ROWS;
    const int wid = threadIdx.x >> 5, lane = threadIdx.x & 31;
    const int gw = blockIdx.x * 8 + wid;

    for (int i = gw; i < nf; i += 64 * 8) {
        int n = g_list[i];
        int b = n >> 11, thw = n & 2047;
#pragma unroll
        for (int j = 0; j < 8; j++) {
            int c = j * 32 + lane;
            zbuf[wid][c] = z[((b * C_DIM + c) << 11) + thw];
        }
        __syncwarp();
        unsigned long long bestk = 0xFFFFFFFFFFFFFFFFull;
#pragma unroll
        for (int j = 0; j < 4; j++) {
            int slot = j * 32 + lane;
            unsigned long long key = (slot < 64)
                ? g_pb[slot * N_ROWS + n]
                : g_ps[(slot - 64) * N_ROWS + n];
            int c = (int)(key & 0xFFFFFFFFull);
            const float4* e4 = (const float4*)(emb + (size_t)c * C_DIM);
            float dot = 0.f;
#pragma unroll 8
            for (int d4 = 0; d4 < 64; d4++) {
                float4 e = e4[d4];
                float4 zv = ((const float4*)zbuf[wid])[d4];
                dot = fmaf(zv.x, e.x, dot);
                dot = fmaf(zv.y, e.y, dot);
                dot = fmaf(zv.z, e.z, dot);
                dot = fmaf(zv.w, e.w, dot);
            }
            float dist = __ldg(&g_enorm[c]) - 2.0f * dot;
            unsigned long long k2 =
                ((unsigned long long)fkey(dist) << 32) | (unsigned)c;
            if (k2 < bestk) bestk = k2;
        }
#pragma unroll
        for (int off = 16; off > 0; off >>= 1) {
            unsigned long long o = __shfl_xor_sync(0xffffffffu, bestk, off);
            if (o < bestk) bestk = o;
        }
        if (lane == 0) atomicMin(&g_fix[n], bestk);
        __syncwarp();
    }
}

// ------- gather + channels-first output + loss + histogram ---------
__global__ void out_kernel(const float* __restrict__ z,
                           const float* __restrict__ emb,
                           float* __restrict__ out) {
    int i = blockIdx.x * blockDim.x + threadIdx.x;
    int b = i >> 19;
    int rem = i & 524287;
    int c = rem >> 11;
    int thw = rem & 2047;
    int n = (b << 11) | thw;
    int idx = g_idx[n];
    if (g_flagged[n]) idx = (int)(g_fix[n] & 0xFFFFFFFFull);
    float e = emb[(size_t)idx * C_DIM + c];
    out[i] = e;
    if (c == 0) {
        out[OUT_EMB + n] = (float)idx;
        atomicAdd(&g_hist[idx], 1);
    }
    float d = z[i] - e;
    float ss = d * d;
#pragma unroll
    for (int o = 16; o > 0; o >>= 1) ss += __shfl_down_sync(0xffffffffu, ss, o);
    __shared__ float ws[8];
    int lane = threadIdx.x & 31, warp = threadIdx.x >> 5;
    if (lane == 0) ws[warp] = ss;
    __syncthreads();
    if (threadIdx.x < 8) {
        float v = ws[threadIdx.x];
#pragma unroll
        for (int o = 4; o > 0; o >>= 1) v += __shfl_down_sync(0xffu, v, o);
        if (threadIdx.x == 0) atomicAdd(&g_accum, (double)v);
    }
}

// ---------------- perplexity + loss finalize ----------------
__global__ void final_kernel(float* __restrict__ out) {
    __shared__ float ws[8];
    int tid = threadIdx.x;
    float s = 0.f;
    for (int k = tid; k < K_CODES; k += 256) {
        float p = (float)g_hist[k] * (1.0f / N_ROWS);
        s += p * logf(p + 1e-10f);
    }
#pragma unroll
    for (int o = 16; o > 0; o >>= 1) s += __shfl_down_sync(0xffffffffu, s, o);
    int lane = tid & 31, warp = tid >> 5;
    if (lane == 0) ws[warp] = s;
    __syncthreads();
    if (tid < 8) {
        float v = ws[tid];
#pragma unroll
        for (int o = 4; o > 0; o >>= 1) v += __shfl_down_sync(0xffu, v, o);
        if (tid == 0) {
            out[OUT_EMB + N_ROWS]     = 0.25f * (float)(g_accum * (1.0 / 2097152.0));
            out[OUT_EMB + N_ROWS + 1] = expf(-v);
        }
    }
}

// ---------------- launch ----------------
extern "C" void kernel_launch(void* const* d_in, const int* in_sizes, int n_in,
                              void* d_out, int out_size) {
    const float* z = (const float*)d_in[0];
    const float* emb = (const float*)d_in[1];
    if (in_sizes[0] == K_CODES * C_DIM && in_sizes[1] == N_ROWS * C_DIM) {
        z = (const float*)d_in[1];
        emb = (const float*)d_in[0];
    }
    float* out = (float*)d_out;

    cudaFuncSetAttribute(vq_gemm, cudaFuncAttributeMaxDynamicSharedMemorySize,
                         SMEM_TOTAL);

    split_z<<<dim3(256, 8), dim3(32, 8)>>>(z);
    split_e<<<2048, 256>>>(emb);
    vq_gemm<<<GRID_P, 256, SMEM_TOTAL>>>();
    merge_kernel<<<32, 256>>>();
    fixup_kernel<<<64, 256>>>(z, emb);
    out_kernel<<<8192, 256>>>(z, emb, out);
    final_kernel<<<1, 256>>>(out);
}

// round 16
// speedup vs baseline: 1.3960x; 1.0455x over previous
#include <cuda_runtime.h>
#include <cuda_fp16.h>
#include <math.h>
#include <float.h>
#include <stdint.h>

#define N_ROWS   8192
#define C_DIM    256
#define K_CODES  16384
#define OUT_EMB  2097152
#define GRID_P   148
#define N_TILES  4096    // 64 m-tiles x 64 n-tiles
#define M_MARGIN 0.25f
#define D_BIAS   512.0f

// ---------------- scratch (static, no allocations) ----------------
__device__ __align__(16) __half g_zh[N_ROWS * C_DIM];
__device__ __align__(16) __half g_eh[K_CODES * C_DIM];
__device__ __align__(16) float g_enorm[K_CODES];
__device__ unsigned long long g_pb[64 * N_ROWS];   // per (nCTA,row) best key
__device__ unsigned long long g_ps[64 * N_ROWS];   // per (nCTA,row) 2nd key
__device__ unsigned long long g_fix[N_ROWS];
__device__ int    g_idx[N_ROWS];
__device__ unsigned char g_flagged[N_ROWS];
__device__ int    g_list[N_ROWS];
__device__ int    g_nflag;
__device__ int    g_hist[K_CODES];
__device__ double g_accum;

// ---------------- PTX helpers (compute_100-legal) ----------------
__device__ __forceinline__ uint32_t smem_u32(const void* p) {
    uint32_t a;
    asm("{ .reg .u64 t; cvta.to.shared.u64 t, %1; cvt.u32.u64 %0, t; }"
        : "=r"(a) : "l"(p));
    return a;
}
__device__ __forceinline__ void cp_async16(uint32_t saddr, const void* gaddr) {
    asm volatile("cp.async.cg.shared.global [%0], [%1], 16;\n"
                 :: "r"(saddr), "l"(gaddr));
}
__device__ __forceinline__ void cp_commit() {
    asm volatile("cp.async.commit_group;\n");
}
template <int N>
__device__ __forceinline__ void cp_wait() {
    asm volatile("cp.async.wait_group %0;\n" :: "n"(N));
}
__device__ __forceinline__ void ldsm4(uint32_t* r, uint32_t addr) {
    asm volatile("ldmatrix.sync.aligned.m8n8.x4.shared.b16 {%0,%1,%2,%3}, [%4];"
                 : "=r"(r[0]), "=r"(r[1]), "=r"(r[2]), "=r"(r[3]) : "r"(addr));
}
__device__ __forceinline__ void mma_f16(float* d, const uint32_t* a,
                                        uint32_t b0, uint32_t b1) {
    asm("mma.sync.aligned.m16n8k16.row.col.f32.f16.f16.f32 "
        "{%0,%1,%2,%3}, {%4,%5,%6,%7}, {%8,%9}, {%0,%1,%2,%3};"
        : "+f"(d[0]), "+f"(d[1]), "+f"(d[2]), "+f"(d[3])
        : "r"(a[0]), "r"(a[1]), "r"(a[2]), "r"(a[3]), "r"(b0), "r"(b1));
}
// first-k16-of-tile variant: C = 0 constants, no accumulator read
__device__ __forceinline__ void mma_f16_z(float* d, const uint32_t* a,
                                          uint32_t b0, uint32_t b1) {
    asm("mma.sync.aligned.m16n8k16.row.col.f32.f16.f16.f32 "
        "{%0,%1,%2,%3}, {%4,%5,%6,%7}, {%8,%9}, {%10,%11,%12,%13};"
        : "=f"(d[0]), "=f"(d[1]), "=f"(d[2]), "=f"(d[3])
        : "r"(a[0]), "r"(a[1]), "r"(a[2]), "r"(a[3]), "r"(b0), "r"(b1),
          "f"(0.f), "f"(0.f), "f"(0.f), "f"(0.f));
}
__device__ __forceinline__ uint32_t fkey(float v) {
    uint32_t u = __float_as_uint(v);
    return (u & 0x80000000u) ? ~u : (u | 0x80000000u);
}

// ------- z [B,C,T,H,W] -> zh fp16 [N, C]; also does global init -------
__global__ void split_z(const float* __restrict__ z) {
    __shared__ float s[32][33];
    int flat = (blockIdx.x * 8 + blockIdx.y) * 256 +
               threadIdx.y * 32 + threadIdx.x;
    if (flat < K_CODES) g_hist[flat] = 0;
    if (flat < N_ROWS) {
        g_fix[flat] = 0xFFFFFFFFFFFFFFFFull;
        g_flagged[flat] = 0;
    }
    if (flat == 0) { g_accum = 0.0; g_nflag = 0; }

    int n0 = blockIdx.x * 32, c0 = blockIdx.y * 32;
    int tx = threadIdx.x, ty = threadIdx.y;
#pragma unroll
    for (int k = 0; k < 4; k++) {
        int yy = ty + k * 8;
        int c = c0 + yy;
        int n = n0 + tx;
        int b = n >> 11, thw = n & 2047;
        s[yy][tx] = z[((b * C_DIM + c) << 11) + thw];
    }
    __syncthreads();
#pragma unroll
    for (int k = 0; k < 4; k++) {
        int yy = ty + k * 8;
        g_zh[(n0 + yy) * C_DIM + c0 + tx] = __float2half_rn(s[tx][yy]);
    }
}

// ---------------- emb -> eh fp16 + ||e||^2 --------------------------
__global__ void split_e(const float* __restrict__ emb) {
    int w = (blockIdx.x * blockDim.x + threadIdx.x) >> 5;
    int lane = threadIdx.x & 31;
    if (w >= K_CODES) return;
    const float4* e4 = (const float4*)(emb + (size_t)w * C_DIM);
    __half2* h2 = (__half2*)(g_eh + (size_t)w * C_DIM);
    float s = 0.f;
#pragma unroll
    for (int q = 0; q < 2; q++) {
        float4 v = e4[q * 32 + lane];
        s += v.x * v.x + v.y * v.y + v.z * v.z + v.w * v.w;
        h2[(q * 32 + lane) * 2 + 0] =
            __halves2half2(__float2half_rn(v.x), __float2half_rn(v.y));
        h2[(q * 32 + lane) * 2 + 1] =
            __halves2half2(__float2half_rn(v.z), __float2half_rn(v.w));
    }
#pragma unroll
    for (int o = 16; o > 0; o >>= 1) s += __shfl_down_sync(0xffffffffu, s, o);
    if (lane == 0) g_enorm[w] = s;
}

// ---------------- persistent 1-term FP16 GEMM + top-2 argmin --------
// 148 persistent CTAs; tile 128(M) x 256(N); 8 warps 2(M) x 4(N), 64x64.
// Tile = 2 k-chunks of 128; cp.async double-buffer pipelined across tiles.
#define STAGE_BYTES 98304
#define CTRL_OFF    196608
#define SMEM_TOTAL  204800

__global__ void __launch_bounds__(256, 1)
vq_gemm() {
    extern __shared__ __align__(1024) char smem[];
    const uint32_t sb = smem_u32(smem);
    const int tid = threadIdx.x;
    const int wid = tid >> 5, l = tid & 31;
    const int warpM = wid >> 2, warpN = wid & 3;

    unsigned long long* sv1 = (unsigned long long*)(smem + CTRL_OFF);
    unsigned long long* sv2 = (unsigned long long*)(smem + CTRL_OFF + 4096);

    uint32_t aoff[4], boff[4];
    int a7[4], b7[4];
#pragma unroll
    for (int mt = 0; mt < 4; mt++) {
        int row = warpM * 64 + mt * 16 + ((l >> 3) & 1) * 8 + (l & 7);
        aoff[mt] = (uint32_t)(row * 256);
        a7[mt] = row & 7;
    }
#pragma unroll
    for (int ntp = 0; ntp < 4; ntp++) {
        int row = warpN * 64 + ntp * 16 + ((l >> 3) & 1) * 8 + (l & 7);
        boff[ntp] = (uint32_t)(row * 256);
        b7[ntp] = row & 7;
    }
    const int segbit = l >> 4;
    // the 16 column offsets this thread owns within the 256-wide tile
    int cloc[16];
#pragma unroll
    for (int nt = 0; nt < 8; nt++)
#pragma unroll
        for (int j = 0; j < 2; j++)
            cloc[nt * 2 + j] = warpN * 64 + (nt >> 1) * 16 + (nt & 1) * 8 +
                               2 * (l & 3) + j;

    const int bid = blockIdx.x;
    const int cnt = (N_TILES - bid + GRID_P - 1) / GRID_P;
    const int P = cnt * 2;

    auto load_pos = [&](int p) {
        const int t = bid + (p >> 1) * GRID_P;
        const int m0 = (t >> 6) << 7;
        const int n0 = (t & 63) << 8;
        const int k0 = (p & 1) * 128;
        const uint32_t base = sb + (p & 1) * STAGE_BYTES;
#pragma unroll
        for (int q = 0; q < 8; q++) {
            int idx = q * 256 + tid;
            int row = idx >> 4, seg = idx & 15;
            uint32_t so = (uint32_t)(row * 256 + ((seg ^ (row & 7)) << 4));
            size_t go = (size_t)(m0 + row) * C_DIM + k0 + seg * 8;
            cp_async16(base + so, g_zh + go);
        }
#pragma unroll
        for (int q = 0; q < 16; q++) {
            int idx = q * 256 + tid;
            int row = idx >> 4, seg = idx & 15;
            uint32_t so = (uint32_t)(row * 256 + ((seg ^ (row & 7)) << 4));
            size_t go = (size_t)(n0 + row) * C_DIM + k0 + seg * 8;
            cp_async16(base + 32768 + so, g_eh + go);
        }
        cp_commit();
    };

    float acc[4][8][4];

    if (P > 0) load_pos(0);
    if (P > 1) load_pos(1);

    for (int p = 0; p < P; p++) {
        if (p + 1 < P) cp_wait<1>(); else cp_wait<0>();
        __syncthreads();
        const uint32_t base = sb + (p & 1) * STAGE_BYTES;
        const bool firstChunk = ((p & 1) == 0);

#pragma unroll
        for (int ks = 0; ks < 8; ks++) {
            const int seg = 2 * ks + segbit;
            uint32_t Ah[4][4];
#pragma unroll
            for (int mt = 0; mt < 4; mt++)
                ldsm4(Ah[mt], base + aoff[mt] + (uint32_t)((seg ^ a7[mt]) << 4));
#pragma unroll
            for (int ntp = 0; ntp < 4; ntp++) {
                uint32_t Bh[4];
                ldsm4(Bh, base + 32768 + boff[ntp] +
                           (uint32_t)((seg ^ b7[ntp]) << 4));
                if (firstChunk && ks == 0) {
#pragma unroll
                    for (int sub = 0; sub < 2; sub++)
#pragma unroll
                        for (int mt = 0; mt < 4; mt++)
                            mma_f16_z(acc[mt][ntp * 2 + sub], Ah[mt],
                                      Bh[sub], Bh[sub + 2]);
                } else {
#pragma unroll
                    for (int sub = 0; sub < 2; sub++)
#pragma unroll
                        for (int mt = 0; mt < 4; mt++)
                            mma_f16(acc[mt][ntp * 2 + sub], Ah[mt],
                                    Bh[sub], Bh[sub + 2]);
                }
            }
        }
        __syncthreads();
        if (p + 2 < P) load_pos(p + 2);

        if ((p & 1) == 1) {
            const int t = bid + (p >> 1) * GRID_P;
            const int m0 = (t >> 6) << 7;
            const int n0 = (t & 63) << 8;
            const int nIdx = t & 63;

            // hoist biased code norms + global indices for my 16 columns
            float en[16];
            uint32_t cidx[16];
#pragma unroll
            for (int q = 0; q < 16; q++) {
                cidx[q] = (uint32_t)(n0 + cloc[q]);
                en[q] = __ldg(&g_enorm[cidx[q]]) + D_BIAS;
            }

#pragma unroll
            for (int s = 0; s < 8; s++) {
                const int mt = s >> 1, half = s & 1;
                const int rloc = warpM * 64 + mt * 16 + half * 8 + (l >> 2);
                unsigned long long k1 = 0xFFFFFFFFFFFFFFFFull;
                unsigned long long k2 = 0xFFFFFFFFFFFFFFFFull;
#pragma unroll
                for (int nt = 0; nt < 8; nt++)
#pragma unroll
                    for (int j = 0; j < 2; j++) {
                        int q = nt * 2 + j;
                        // d + 512 > 0 always -> raw bits order-isomorphic
                        float d = en[q] - 2.0f * acc[mt][nt][half * 2 + j];
                        unsigned long long key =
                            ((unsigned long long)__float_as_uint(d) << 32) |
                            cidx[q];
                        if (key < k1) { k2 = k1; k1 = key; }
                        else if (key < k2) { k2 = key; }
                    }
#pragma unroll
                for (int off = 1; off <= 2; off <<= 1) {
                    unsigned long long o1 =
                        __shfl_xor_sync(0xffffffffu, k1, off);
                    unsigned long long o2 =
                        __shfl_xor_sync(0xffffffffu, k2, off);
                    unsigned long long hi = (k1 > o1) ? k1 : o1;
                    k1 = (k1 < o1) ? k1 : o1;
                    unsigned long long lo2 = (k2 < o2) ? k2 : o2;
                    k2 = (hi < lo2) ? hi : lo2;
                }
                if ((l & 3) == 0) {
                    sv1[warpN * 128 + rloc] = k1;
                    sv2[warpN * 128 + rloc] = k2;
                }
            }
            __syncthreads();
            if (tid < 128) {
                unsigned long long K1 = sv1[tid];
                unsigned long long K2 = sv2[tid];
#pragma unroll
                for (int w = 1; w < 4; w++) {
                    unsigned long long b1 = sv1[w * 128 + tid];
                    unsigned long long b2 = sv2[w * 128 + tid];
                    unsigned long long hi = (K1 > b1) ? K1 : b1;
                    K1 = (K1 < b1) ? K1 : b1;
                    unsigned long long lo2 = (K2 < b2) ? K2 : b2;
                    K2 = (hi < lo2) ? hi : lo2;
                }
                g_pb[nIdx * N_ROWS + m0 + tid] = K1;
                g_ps[nIdx * N_ROWS + m0 + tid] = K2;
            }
        }
    }
}

// ---------------- merge: global top-2 per row, flag close rows ------
// keys hold RAW float bits of (dist + 512) in the high word
__global__ void merge_kernel() {
    int n = blockIdx.x * blockDim.x + threadIdx.x;
    if (n >= N_ROWS) return;
    unsigned long long k1 = 0xFFFFFFFFFFFFFFFFull;
    unsigned long long k2 = 0xFFFFFFFFFFFFFFFFull;
    int cstar = 0;
    for (int c = 0; c < 64; c++) {
        unsigned long long kb = g_pb[c * N_ROWS + n];
        if (kb < k1) { k2 = k1; k1 = kb; cstar = c; }
        else if (kb < k2) { k2 = kb; }
    }
    unsigned long long ks2 = g_ps[cstar * N_ROWS + n];
    if (ks2 < k2) k2 = ks2;
    g_idx[n] = (int)(k1 & 0xFFFFFFFFull);
    float v1 = __uint_as_float((uint32_t)(k1 >> 32));
    float v2 = __uint_as_float((uint32_t)(k2 >> 32));
    if (v2 - v1 < M_MARGIN) {
        g_flagged[n] = 1;
        int pos = atomicAdd(&g_nflag, 1);
        if (pos < N_ROWS) g_list[pos] = n;
    }
}

// ------- exact fp32 rescue over the 128 stored candidates/row -------
__global__ void fixup_kernel(const float* __restrict__ z,
                             const float* __restrict__ emb) {
    __shared__ __align__(16) float zbuf[8][256];
    int nf = g_nflag;
    if (nf > N_ROWS) nf = N_ROWS;
    const int wid = threadIdx.x >> 5, lane = threadIdx.x & 31;
    const int gw = blockIdx.x * 8 + wid;

    for (int i = gw; i < nf; i += 64 * 8) {
        int n = g_list[i];
        int b = n >> 11, thw = n & 2047;
#pragma unroll
        for (int j = 0; j < 8; j++) {
            int c = j * 32 + lane;
            zbuf[wid][c] = z[((b * C_DIM + c) << 11) + thw];
        }
        __syncwarp();
        unsigned long long bestk = 0xFFFFFFFFFFFFFFFFull;
#pragma unroll
        for (int j = 0; j < 4; j++) {
            int slot = j * 32 + lane;
            unsigned long long key = (slot < 64)
                ? g_pb[slot * N_ROWS + n]
                : g_ps[(slot - 64) * N_ROWS + n];
            int c = (int)(key & 0xFFFFFFFFull);
            const float4* e4 = (const float4*)(emb + (size_t)c * C_DIM);
            float dot = 0.f;
#pragma unroll 8
            for (int d4 = 0; d4 < 64; d4++) {
                float4 e = e4[d4];
                float4 zv = ((const float4*)zbuf[wid])[d4];
                dot = fmaf(zv.x, e.x, dot);
                dot = fmaf(zv.y, e.y, dot);
                dot = fmaf(zv.z, e.z, dot);
                dot = fmaf(zv.w, e.w, dot);
            }
            float dist = __ldg(&g_enorm[c]) - 2.0f * dot;
            unsigned long long k2 =
                ((unsigned long long)fkey(dist) << 32) | (unsigned)c;
            if (k2 < bestk) bestk = k2;
        }
#pragma unroll
        for (int off = 16; off > 0; off >>= 1) {
            unsigned long long o = __shfl_xor_sync(0xffffffffu, bestk, off);
            if (o < bestk) bestk = o;
        }
        if (lane == 0) atomicMin(&g_fix[n], bestk);
        __syncwarp();
    }
}

// ------- gather + channels-first output + loss + histogram ---------
__global__ void out_kernel(const float* __restrict__ z,
                           const float* __restrict__ emb,
                           float* __restrict__ out) {
    int i = blockIdx.x * blockDim.x + threadIdx.x;
    int b = i >> 19;
    int rem = i & 524287;
    int c = rem >> 11;
    int thw = rem & 2047;
    int n = (b << 11) | thw;
    int idx = g_idx[n];
    if (g_flagged[n]) idx = (int)(g_fix[n] & 0xFFFFFFFFull);
    float e = emb[(size_t)idx * C_DIM + c];
    out[i] = e;
    if (c == 0) {
        out[OUT_EMB + n] = (float)idx;
        atomicAdd(&g_hist[idx], 1);
    }
    float d = z[i] - e;
    float ss = d * d;
#pragma unroll
    for (int o = 16; o > 0; o >>= 1) ss += __shfl_down_sync(0xffffffffu, ss, o);
    __shared__ float ws[8];
    int lane = threadIdx.x & 31, warp = threadIdx.x >> 5;
    if (lane == 0) ws[warp] = ss;
    __syncthreads();
    if (threadIdx.x < 8) {
        float v = ws[threadIdx.x];
#pragma unroll
        for (int o = 4; o > 0; o >>= 1) v += __shfl_down_sync(0xffu, v, o);
        if (threadIdx.x == 0) atomicAdd(&g_accum, (double)v);
    }
}

// ---------------- perplexity + loss finalize ----------------
__global__ void final_kernel(float* __restrict__ out) {
    __shared__ float ws[8];
    int tid = threadIdx.x;
    float s = 0.f;
    for (int k = tid; k < K_CODES; k += 256) {
        float p = (float)g_hist[k] * (1.0f / N_ROWS);
        s += p * logf(p + 1e-10f);
    }
#pragma unroll
    for (int o = 16; o > 0; o >>= 1) s += __shfl_down_sync(0xffffffffu, s, o);
    int lane = tid & 31, warp = tid >> 5;
    if (lane == 0) ws[warp] = s;
    __syncthreads();
    if (tid < 8) {
        float v = ws[tid];
#pragma unroll
        for (int o = 4; o > 0; o >>= 1) v += __shfl_down_sync(0xffu, v, o);
        if (tid == 0) {
            out[OUT_EMB + N_ROWS]     = 0.25f * (float)(g_accum * (1.0 / 2097152.0));
            out[OUT_EMB + N_ROWS + 1] = expf(-v);
        }
    }
}

// ---------------- launch ----------------
extern "C" void kernel_launch(void* const* d_in, const int* in_sizes, int n_in,
                              void* d_out, int out_size) {
    const float* z = (const float*)d_in[0];
    const float* emb = (const float*)d_in[1];
    if (in_sizes[0] == K_CODES * C_DIM && in_sizes[1] == N_ROWS * C_DIM) {
        z = (const float*)d_in[1];
        emb = (const float*)d_in[0];
    }
    float* out = (float*)d_out;

    cudaFuncSetAttribute(vq_gemm, cudaFuncAttributeMaxDynamicSharedMemorySize,
                         SMEM_TOTAL);

    split_z<<<dim3(256, 8), dim3(32, 8)>>>(z);
    split_e<<<2048, 256>>>(emb);
    vq_gemm<<<GRID_P, 256, SMEM_TOTAL>>>();
    merge_kernel<<<32, 256>>>();
    fixup_kernel<<<64, 256>>>(z, emb);
    out_kernel<<<8192, 256>>>(z, emb, out);
    final_kernel<<<1, 256>>>(out);
}